// round 14
// baseline (speedup 1.0000x reference)
#include <cuda_runtime.h>
#include <math.h>
#include <stdint.h>

// Problem constants (fixed by setup_inputs)
#define B_      2
#define C_      2048
#define D_      256
#define H_      8
#define L_      4
#define FF_     2048
#define DH_     32
#define NOUT_   16384
#define M_      (B_ * C_)      // 4096
#define KTOK_   60

// -------------------- scratch --------------------
__device__ float g_x [M_ * D_];
__device__ float g_h [M_ * D_];
__device__ float g_q [M_ * D_];
__device__ float g_k [M_ * D_];
__device__ float g_v [M_ * D_];
__device__ float g_ao[M_ * D_];
__device__ float g_ff[M_ * FF_];
__device__ float g_cos[C_ * 16];
__device__ float g_sin[C_ * 16];
// pre-quantized (tf32) weights
__device__ float g_wq[L_ * D_ * D_];
__device__ float g_wk[L_ * D_ * D_];
__device__ float g_wv[L_ * D_ * D_];
__device__ float g_wo[L_ * D_ * D_];
__device__ float g_w1[L_ * D_ * FF_];
__device__ float g_w2[L_ * FF_ * D_];
__device__ float g_wout[D_ * NOUT_];

// TF32 input quantization (round-to-nearest-away), matching cuBLAS/XLA TF32 matmuls.
__device__ __forceinline__ float tf32r(float x) {
    float r;
    asm("cvt.rna.tf32.f32 %0, %1;" : "=f"(r) : "f"(x));
    return r;
}

__device__ __forceinline__ void cp16(uint32_t saddr, const float* gptr) {
    asm volatile("cp.async.cg.shared.global [%0], [%1], 16;" :: "r"(saddr), "l"(gptr));
}
__device__ __forceinline__ void cp_commit() {
    asm volatile("cp.async.commit_group;" ::: "memory");
}
template<int N>
__device__ __forceinline__ void cp_wait() {
    asm volatile("cp.async.wait_group %0;" :: "n"(N) : "memory");
}

// -------------------- fused weight-prequant + RoPE-tables kernel -----------------------
#define SEG_A  (L_ * D_ * D_ / 4)        // 65536 per qkv/o weight
#define SEG_W  (L_ * D_ * FF_ / 4)       // 524288 per w1/w2
#define SEG_O  (D_ * NOUT_ / 4)          // 1048576
#define PQ_TOTAL (4 * SEG_A + 2 * SEG_W + SEG_O)
#define PQ_ALL   (PQ_TOTAL + C_ * 16)

__global__ void prequant_kernel(
    const float* __restrict__ Wq, const float* __restrict__ Wk,
    const float* __restrict__ Wv, const float* __restrict__ Wo,
    const float* __restrict__ W1, const float* __restrict__ W2,
    const float* __restrict__ Wout)
{
    int i = blockIdx.x * blockDim.x + threadIdx.x;
    if (i >= PQ_ALL) return;
    if (i >= PQ_TOTAL) {
        const int t = i - PQ_TOTAL;
        const int fi = t & 15;
        const int c  = t >> 4;
        const float invf = (float)(1.0 / pow(10000.0, (double)fi / 16.0));
        const float angf = (float)c * invf;
        g_cos[t] = (float)cos((double)angf);
        g_sin[t] = (float)sin((double)angf);
        return;
    }
    const float* src; float* dst;
    if      (i < 1 * SEG_A)             { src = Wq;  dst = g_wq;   i -= 0 * SEG_A; }
    else if (i < 2 * SEG_A)             { src = Wk;  dst = g_wk;   i -= 1 * SEG_A; }
    else if (i < 3 * SEG_A)             { src = Wv;  dst = g_wv;   i -= 2 * SEG_A; }
    else if (i < 4 * SEG_A)             { src = Wo;  dst = g_wo;   i -= 3 * SEG_A; }
    else if (i < 4 * SEG_A + SEG_W)     { src = W1;  dst = g_w1;   i -= 4 * SEG_A; }
    else if (i < 4 * SEG_A + 2 * SEG_W) { src = W2;  dst = g_w2;   i -= 4 * SEG_A + SEG_W; }
    else                                { src = Wout;dst = g_wout; i -= 4 * SEG_A + 2 * SEG_W; }
    float4 a = ((const float4*)src)[i];
    a.x = tf32r(a.x); a.y = tf32r(a.y); a.z = tf32r(a.z); a.w = tf32r(a.w);
    ((float4*)dst)[i] = a;
}

// ==================== TF32 HMMA GEMM, 2-stage cp.async (proven R10 config) ==============
// All inputs PRE-QUANTIZED tf32 values. C = A@B [+bias] [+res] [relu] [tf32-out].
// KSPLIT2: blockIdx.z selects K-half. ROPEQK: fuse RoPE+quantize into epilogue for z<2.
template<int BM, int BN, int WM_, int WN_, bool RELU, bool RES, bool QKV3, bool QOUT,
         bool BIASF, bool KSPLIT2, bool ROPEQK>
__global__ void tgemm_kernel(
    const float* __restrict__ A,
    const float* __restrict__ B0, const float* __restrict__ bias0, float* __restrict__ C0,
    const float* __restrict__ res,
    int N, int K, int lda,
    const float* B1, const float* bias1, float* C1,
    const float* B2, const float* bias2, float* C2)
{
    constexpr int THREADS = WM_ * WN_ * 32;
    constexpr int AST = 36;
    constexpr int BST = BN + 8;
    constexpr int FM  = (BM / WM_) / 16;
    constexpr int FN  = (BN / WN_) / 8;

    extern __shared__ float smem[];
    float* As = smem;                     // [2][BM][AST]
    float* Bs = smem + 2 * BM * AST;      // [2][32][BST]

    const float* Ap = A;
    const float* Bm = B0;  const float* bias = bias0;  float* Cm = C0;
    if (QKV3) {
        if (blockIdx.z == 1)      { Bm = B1; bias = bias1; Cm = C1; }
        else if (blockIdx.z == 2) { Bm = B2; bias = bias2; Cm = C2; }
    }
    if (KSPLIT2) {
        if (blockIdx.z == 1) { Ap = A + K; Bm = B1; Cm = C1; }
    }

    const int tid  = threadIdx.x;
    const int warp = tid >> 5;
    const int lane = tid & 31;
    const int wm   = warp / WN_;
    const int wn   = warp % WN_;
    const int gid  = lane >> 2;
    const int tid4 = lane & 3;

    const int row0 = blockIdx.y * BM;
    const int col0 = blockIdx.x * BN;

    float acc[FM][FN][4];
#pragma unroll
    for (int i = 0; i < FM; i++)
#pragma unroll
        for (int j = 0; j < FN; j++)
#pragma unroll
            for (int t = 0; t < 4; t++) acc[i][j][t] = 0.f;

    const int nk = K >> 5;

    auto issue = [&](int t, int buf) {
        const int k0 = t << 5;
        float* Ad = As + buf * BM * AST;
        float* Bd = Bs + buf * 32 * BST;
#pragma unroll
        for (int i = 0; i < (BM * 8) / THREADS; i++) {
            const int idx = tid + i * THREADS;
            const int r   = idx >> 3;
            const int k4  = (idx & 7) * 4;
            cp16((uint32_t)__cvta_generic_to_shared(Ad + r * AST + k4),
                 Ap + (size_t)(row0 + r) * lda + k0 + k4);
        }
#pragma unroll
        for (int i = 0; i < (BN * 8) / THREADS; i++) {
            const int idx = tid + i * THREADS;
            const int kr  = idx / (BN / 4);
            const int c4  = (idx % (BN / 4)) * 4;
            cp16((uint32_t)__cvta_generic_to_shared(Bd + kr * BST + c4),
                 Bm + (size_t)(k0 + kr) * N + col0 + c4);
        }
        cp_commit();
    };

    issue(0, 0);
    for (int t = 0; t < nk; t++) {
        if (t + 1 < nk) { issue(t + 1, (t + 1) & 1); cp_wait<1>(); }
        else            { cp_wait<0>(); }
        __syncthreads();

        const float* Ab = As + (t & 1) * BM * AST;
        const float* Bb = Bs + (t & 1) * 32 * BST;
#pragma unroll
        for (int kk = 0; kk < 32; kk += 8) {
            uint32_t af[FM][4];
#pragma unroll
            for (int mf = 0; mf < FM; mf++) {
                const int ar = wm * (BM / WM_) + mf * 16 + gid;
                af[mf][0] = __float_as_uint(Ab[(ar    ) * AST + kk + tid4    ]);
                af[mf][1] = __float_as_uint(Ab[(ar + 8) * AST + kk + tid4    ]);
                af[mf][2] = __float_as_uint(Ab[(ar    ) * AST + kk + tid4 + 4]);
                af[mf][3] = __float_as_uint(Ab[(ar + 8) * AST + kk + tid4 + 4]);
            }
            uint32_t bf[FN][2];
#pragma unroll
            for (int nf = 0; nf < FN; nf++) {
                const int bc = wn * (BN / WN_) + nf * 8 + gid;
                bf[nf][0] = __float_as_uint(Bb[(kk + tid4    ) * BST + bc]);
                bf[nf][1] = __float_as_uint(Bb[(kk + tid4 + 4) * BST + bc]);
            }
#pragma unroll
            for (int mf = 0; mf < FM; mf++)
#pragma unroll
                for (int nf = 0; nf < FN; nf++) {
                    asm volatile(
                        "mma.sync.aligned.m16n8k8.row.col.f32.tf32.tf32.f32 "
                        "{%0,%1,%2,%3}, {%4,%5,%6,%7}, {%8,%9}, {%0,%1,%2,%3};"
                        : "+f"(acc[mf][nf][0]), "+f"(acc[mf][nf][1]),
                          "+f"(acc[mf][nf][2]), "+f"(acc[mf][nf][3])
                        : "r"(af[mf][0]), "r"(af[mf][1]), "r"(af[mf][2]), "r"(af[mf][3]),
                          "r"(bf[nf][0]), "r"(bf[nf][1]));
                }
        }
        __syncthreads();
    }

    // ---------------- Epilogue ----------------
    if (ROPEQK) {
        const bool doRope = (blockIdx.z < 2);
#pragma unroll
        for (int mf = 0; mf < FM; mf++) {
            const int r = row0 + wm * (BM / WM_) + mf * 16 + gid;
            float val[FN][4];
#pragma unroll
            for (int nf = 0; nf < FN; nf++) {
                const int c = col0 + wn * (BN / WN_) + nf * 8 + tid4 * 2;
                val[nf][0] = acc[mf][nf][0] + bias[c];
                val[nf][1] = acc[mf][nf][1] + bias[c + 1];
                val[nf][2] = acc[mf][nf][2] + bias[c];
                val[nf][3] = acc[mf][nf][3] + bias[c + 1];
            }
            if (doRope) {
                const int tok1 = r & (C_ - 1);
                const int tok2 = (r + 8) & (C_ - 1);
#pragma unroll
                for (int nf = 0; nf < 2; nf++) {
                    const int i0 = nf * 8 + tid4 * 2;
                    float cs, sn, t1, t2;
                    cs = g_cos[tok1 * 16 + i0];     sn = g_sin[tok1 * 16 + i0];
                    t1 = val[nf][0]; t2 = val[nf + 2][0];
                    val[nf][0]     = t1 * cs - t2 * sn;
                    val[nf + 2][0] = t1 * sn + t2 * cs;
                    cs = g_cos[tok1 * 16 + i0 + 1]; sn = g_sin[tok1 * 16 + i0 + 1];
                    t1 = val[nf][1]; t2 = val[nf + 2][1];
                    val[nf][1]     = t1 * cs - t2 * sn;
                    val[nf + 2][1] = t1 * sn + t2 * cs;
                    cs = g_cos[tok2 * 16 + i0];     sn = g_sin[tok2 * 16 + i0];
                    t1 = val[nf][2]; t2 = val[nf + 2][2];
                    val[nf][2]     = t1 * cs - t2 * sn;
                    val[nf + 2][2] = t1 * sn + t2 * cs;
                    cs = g_cos[tok2 * 16 + i0 + 1]; sn = g_sin[tok2 * 16 + i0 + 1];
                    t1 = val[nf][3]; t2 = val[nf + 2][3];
                    val[nf][3]     = t1 * cs - t2 * sn;
                    val[nf + 2][3] = t1 * sn + t2 * cs;
                }
#pragma unroll
                for (int nf = 0; nf < FN; nf++)
#pragma unroll
                    for (int t = 0; t < 4; t++) val[nf][t] = tf32r(val[nf][t]);
            }
#pragma unroll
            for (int nf = 0; nf < FN; nf++) {
                const int c = col0 + wn * (BN / WN_) + nf * 8 + tid4 * 2;
                *(float2*)(Cm + (size_t)r * N + c)       = make_float2(val[nf][0], val[nf][1]);
                *(float2*)(Cm + (size_t)(r + 8) * N + c) = make_float2(val[nf][2], val[nf][3]);
            }
        }
    } else {
#pragma unroll
        for (int mf = 0; mf < FM; mf++) {
            const int r = row0 + wm * (BM / WM_) + mf * 16 + gid;
#pragma unroll
            for (int nf = 0; nf < FN; nf++) {
                const int c = col0 + wn * (BN / WN_) + nf * 8 + tid4 * 2;
                float v0 = acc[mf][nf][0];
                float v1 = acc[mf][nf][1];
                float v2 = acc[mf][nf][2];
                float v3 = acc[mf][nf][3];
                if (BIASF) {
                    v0 += bias[c]; v1 += bias[c + 1]; v2 += bias[c]; v3 += bias[c + 1];
                }
                if (RES) {
                    const float2 r0 = *(const float2*)(res + (size_t)r * N + c);
                    const float2 r1 = *(const float2*)(res + (size_t)(r + 8) * N + c);
                    v0 += r0.x; v1 += r0.y; v2 += r1.x; v3 += r1.y;
                }
                if (RELU) {
                    v0 = fmaxf(v0, 0.f); v1 = fmaxf(v1, 0.f);
                    v2 = fmaxf(v2, 0.f); v3 = fmaxf(v3, 0.f);
                }
                if (QOUT) {
                    v0 = tf32r(v0); v1 = tf32r(v1); v2 = tf32r(v2); v3 = tf32r(v3);
                }
                *(float2*)(Cm + (size_t)r * N + c)       = make_float2(v0, v1);
                *(float2*)(Cm + (size_t)(r + 8) * N + c) = make_float2(v2, v3);
            }
        }
    }
}

// -------------------- fused FF2-reduce + layernorm (warp/row) --------------------------
__global__ __launch_bounds__(256) void redln_kernel(
    const float* __restrict__ p0, const float* __restrict__ p1,
    const float* __restrict__ b2, float* __restrict__ x,
    const float* __restrict__ g, const float* __restrict__ b, float* __restrict__ out)
{
    const int row  = blockIdx.x * 8 + (threadIdx.x >> 5);
    const int lane = threadIdx.x & 31;
    const size_t base = (size_t)row * D_;

    float4 a0, a1;
    {
        const float4 xa = ((const float4*)(x + base))[lane];
        const float4 xb = ((const float4*)(x + base))[lane + 32];
        const float4 pa = ((const float4*)(p0 + base))[lane];
        const float4 pb = ((const float4*)(p0 + base))[lane + 32];
        const float4 qa = ((const float4*)(p1 + base))[lane];
        const float4 qb = ((const float4*)(p1 + base))[lane + 32];
        const float4 ba = ((const float4*)b2)[lane];
        const float4 bb = ((const float4*)b2)[lane + 32];
        a0.x = xa.x + (pa.x + qa.x + ba.x);
        a0.y = xa.y + (pa.y + qa.y + ba.y);
        a0.z = xa.z + (pa.z + qa.z + ba.z);
        a0.w = xa.w + (pa.w + qa.w + ba.w);
        a1.x = xb.x + (pb.x + qb.x + bb.x);
        a1.y = xb.y + (pb.y + qb.y + bb.y);
        a1.z = xb.z + (pb.z + qb.z + bb.z);
        a1.w = xb.w + (pb.w + qb.w + bb.w);
        ((float4*)(x + base))[lane]      = a0;
        ((float4*)(x + base))[lane + 32] = a1;
    }

    float s  = a0.x + a0.y + a0.z + a0.w + a1.x + a1.y + a1.z + a1.w;
    float s2 = a0.x*a0.x + a0.y*a0.y + a0.z*a0.z + a0.w*a0.w
             + a1.x*a1.x + a1.y*a1.y + a1.z*a1.z + a1.w*a1.w;
#pragma unroll
    for (int o = 16; o > 0; o >>= 1) {
        s  += __shfl_xor_sync(0xffffffffu, s,  o);
        s2 += __shfl_xor_sync(0xffffffffu, s2, o);
    }
    const float mean = s  * (1.f / 256.f);
    const float var  = s2 * (1.f / 256.f) - mean * mean;
    const float rs   = rsqrtf(var + 1e-5f);

    const float4 g0 = ((const float4*)g)[lane];
    const float4 g1 = ((const float4*)g)[lane + 32];
    const float4 b0 = ((const float4*)b)[lane];
    const float4 b1 = ((const float4*)b)[lane + 32];
    float4* op = (float4*)(out + base);
    op[lane]      = make_float4(tf32r((a0.x-mean)*rs*g0.x + b0.x), tf32r((a0.y-mean)*rs*g0.y + b0.y),
                                tf32r((a0.z-mean)*rs*g0.z + b0.z), tf32r((a0.w-mean)*rs*g0.w + b0.w));
    op[lane + 32] = make_float4(tf32r((a1.x-mean)*rs*g1.x + b1.x), tf32r((a1.y-mean)*rs*g1.y + b1.y),
                                tf32r((a1.z-mean)*rs*g1.z + b1.z), tf32r((a1.w-mean)*rs*g1.w + b1.w));
}

// -------------------- fused final FF2-reduce + tf32 quantize ---------------------------
__global__ void redq_kernel(
    const float* __restrict__ p0, const float* __restrict__ p1,
    const float* __restrict__ b2, const float* __restrict__ x, float* __restrict__ xq)
{
    const int i = blockIdx.x * blockDim.x + threadIdx.x;
    const int c = i & (D_ / 4 - 1);
    const float4 a = ((const float4*)p0)[i];
    const float4 b = ((const float4*)p1)[i];
    const float4 bb = ((const float4*)b2)[c];
    const float4 xx = ((const float4*)x)[i];
    float4 o;
    o.x = tf32r(xx.x + (a.x + b.x + bb.x));
    o.y = tf32r(xx.y + (a.y + b.y + bb.y));
    o.z = tf32r(xx.z + (a.z + b.z + bb.z));
    o.w = tf32r(xx.w + (a.w + b.w + bb.w));
    ((float4*)xq)[i] = o;
}

// -------------------- FFMA GEMM for the K=8 embed only --------------------
__global__ __launch_bounds__(256) void embed_kernel(
    const float* __restrict__ A, const float* __restrict__ Bm,
    const float* __restrict__ bias, float* __restrict__ Cm, int M, int N, int K)
{
    __shared__ float As[8][128];
    __shared__ float Bs[8][128];
    const int tid  = threadIdx.x;
    const int tx   = tid & 15;
    const int ty   = tid >> 4;
    const int row0 = blockIdx.y * 128;
    const int col0 = blockIdx.x * 128;
    const int aRow = tid >> 1;
    const int aCol = (tid & 1) * 4;
    const int bRow = tid >> 5;
    const int bCol = (tid & 31) * 4;

    float acc[8][8];
#pragma unroll
    for (int i = 0; i < 8; i++)
#pragma unroll
        for (int j = 0; j < 8; j++) acc[i][j] = 0.f;

    for (int k0 = 0; k0 < K; k0 += 8) {
        float4 a4 = *(const float4*)(A + (size_t)(row0 + aRow) * K + k0 + aCol);
        As[aCol + 0][aRow] = tf32r(a4.x);
        As[aCol + 1][aRow] = tf32r(a4.y);
        As[aCol + 2][aRow] = tf32r(a4.z);
        As[aCol + 3][aRow] = tf32r(a4.w);
        float4 b4 = *(const float4*)(Bm + (size_t)(k0 + bRow) * N + col0 + bCol);
        Bs[bRow][bCol + 0] = tf32r(b4.x);
        Bs[bRow][bCol + 1] = tf32r(b4.y);
        Bs[bRow][bCol + 2] = tf32r(b4.z);
        Bs[bRow][bCol + 3] = tf32r(b4.w);
        __syncthreads();
#pragma unroll
        for (int kk = 0; kk < 8; kk++) {
            float ra[8], rb[8];
#pragma unroll
            for (int i = 0; i < 8; i++) ra[i] = As[kk][ty * 8 + i];
#pragma unroll
            for (int j = 0; j < 8; j++) rb[j] = Bs[kk][tx * 8 + j];
#pragma unroll
            for (int i = 0; i < 8; i++)
#pragma unroll
                for (int j = 0; j < 8; j++)
                    acc[i][j] += ra[i] * rb[j];
        }
        __syncthreads();
    }
#pragma unroll
    for (int i = 0; i < 8; i++) {
        int r = row0 + ty * 8 + i;
#pragma unroll
        for (int j = 0; j < 8; j++) {
            int c = col0 + tx * 8 + j;
            Cm[(size_t)r * N + c] = acc[i][j] + bias[c];
        }
    }
}

// -------------------- layernorm (warp/row, float4); OUTPUT IS TF32-QUANTIZED -----------
__global__ __launch_bounds__(256) void ln_kernel(
    const float* __restrict__ x, const float* __restrict__ g,
    const float* __restrict__ b, float* __restrict__ out)
{
    const int row  = blockIdx.x * 8 + (threadIdx.x >> 5);
    const int lane = threadIdx.x & 31;
    const float4* xp = (const float4*)(x + (size_t)row * D_);
    const float4 a0 = xp[lane];
    const float4 a1 = xp[lane + 32];

    float s  = a0.x + a0.y + a0.z + a0.w + a1.x + a1.y + a1.z + a1.w;
    float s2 = a0.x*a0.x + a0.y*a0.y + a0.z*a0.z + a0.w*a0.w
             + a1.x*a1.x + a1.y*a1.y + a1.z*a1.z + a1.w*a1.w;
#pragma unroll
    for (int o = 16; o > 0; o >>= 1) {
        s  += __shfl_xor_sync(0xffffffffu, s,  o);
        s2 += __shfl_xor_sync(0xffffffffu, s2, o);
    }
    const float mean = s  * (1.f / 256.f);
    const float var  = s2 * (1.f / 256.f) - mean * mean;
    const float rs   = rsqrtf(var + 1e-5f);

    const float4 g0 = ((const float4*)g)[lane];
    const float4 g1 = ((const float4*)g)[lane + 32];
    const float4 b0 = ((const float4*)b)[lane];
    const float4 b1 = ((const float4*)b)[lane + 32];
    float4* op = (float4*)(out + (size_t)row * D_);
    op[lane]      = make_float4(tf32r((a0.x-mean)*rs*g0.x + b0.x), tf32r((a0.y-mean)*rs*g0.y + b0.y),
                                tf32r((a0.z-mean)*rs*g0.z + b0.z), tf32r((a0.w-mean)*rs*g0.w + b0.w));
    op[lane + 32] = make_float4(tf32r((a1.x-mean)*rs*g1.x + b1.x), tf32r((a1.y-mean)*rs*g1.y + b1.y),
                                tf32r((a1.z-mean)*rs*g1.z + b1.z), tf32r((a1.w-mean)*rs*g1.w + b1.w));
}

// -------------------- windowed circular attention (8 keys / 2 shfls per iter) ----------
// lane = g*4 + s:  g = key offset 0..7, s = dim-octet 0..3 (dims [8s, 8s+8)).
// Phase 1 computes 64 scores (keys 60..63 masked later). Phase 3 zero-weights j>=60.
__global__ __launch_bounds__(128) void attn_kernel(
    const float* __restrict__ q, const float* __restrict__ k,
    const float* __restrict__ v, float* __restrict__ out)
{
    __shared__ float wbuf[4][64];
    const int warp = (blockIdx.x * blockDim.x + threadIdx.x) >> 5;  // (b,h,c)
    const int wib  = (threadIdx.x >> 5);
    const int lane = threadIdx.x & 31;
    const int g    = lane >> 2;        // 0..7
    const int s    = lane & 3;         // 0..3
    const int c = warp & (C_ - 1);
    const int h = (warp >> 11) & (H_ - 1);
    const int b = warp >> 14;
    const int qrow = b * C_ + c;
    const float scale = 0.17677669529663687f;                       // 1/sqrt(32)

    const float4* qp = (const float4*)(q + (size_t)qrow * D_ + h * DH_);
    const float4 qa = qp[s * 2];
    const float4 qb = qp[s * 2 + 1];

    // Phase 1: 8 keys per iteration, 2-shfl reduction within each 4-lane quad group
#pragma unroll
    for (int j0 = 0; j0 < 64; j0 += 8) {
        const int j = j0 + g;
        int kc = c - j; if (kc < 0) kc += C_;
        const float4* kp = (const float4*)(k + (size_t)(b * C_ + kc) * D_ + h * DH_);
        const float4 ka = kp[s * 2];
        const float4 kb = kp[s * 2 + 1];
        float p = qa.x * ka.x + qa.y * ka.y + qa.z * ka.z + qa.w * ka.w
                + qb.x * kb.x + qb.y * kb.y + qb.z * kb.z + qb.w * kb.w;
        p += __shfl_xor_sync(0xffffffffu, p, 1);
        p += __shfl_xor_sync(0xffffffffu, p, 2);
        if (s == 0) wbuf[wib][j] = p * scale;
    }
    __syncwarp();

    // Phase 2: max + denom (parallel over lanes; wbuf[60..63] never read)
    const float v1 = wbuf[wib][lane];
    const float v2 = (lane < KTOK_ - 32) ? wbuf[wib][lane + 32] : -INFINITY;
    float m = fmaxf(v1, v2);
#pragma unroll
    for (int o = 16; o > 0; o >>= 1) m = fmaxf(m, __shfl_xor_sync(0xffffffffu, m, o));
    const float p1 = __expf(v1 - m);
    const float p2 = (lane < KTOK_ - 32) ? __expf(v2 - m) : 0.f;
    wbuf[wib][lane] = p1;
    if (lane < KTOK_ - 32) wbuf[wib][lane + 32] = p2;
    float d = p1 + p2;
#pragma unroll
    for (int o = 16; o > 0; o >>= 1) d += __shfl_xor_sync(0xffffffffu, d, o);
    const float invd = 1.f / d;
    __syncwarp();

    // Phase 3: 8 keys per iteration, no in-loop shfls; j>=60 weight forced to 0
    float4 aca = make_float4(0.f, 0.f, 0.f, 0.f);
    float4 acb = make_float4(0.f, 0.f, 0.f, 0.f);
#pragma unroll
    for (int j0 = 0; j0 < 64; j0 += 8) {
        const int j = j0 + g;
        int kc = c - j; if (kc < 0) kc += C_;
        const float4* vp = (const float4*)(v + (size_t)(b * C_ + kc) * D_ + h * DH_);
        const float4 va = vp[s * 2];
        const float4 vb = vp[s * 2 + 1];
        const float w = (j < KTOK_) ? tf32r(wbuf[wib][j] * invd) : 0.f;
        aca.x += w * tf32r(va.x);
        aca.y += w * tf32r(va.y);
        aca.z += w * tf32r(va.z);
        aca.w += w * tf32r(va.w);
        acb.x += w * tf32r(vb.x);
        acb.y += w * tf32r(vb.y);
        acb.z += w * tf32r(vb.z);
        acb.w += w * tf32r(vb.w);
    }
    // reduce across the 8 g-groups (lanes differing in bits 2..4)
#pragma unroll
    for (int o = 4; o <= 16; o <<= 1) {
        aca.x += __shfl_xor_sync(0xffffffffu, aca.x, o);
        aca.y += __shfl_xor_sync(0xffffffffu, aca.y, o);
        aca.z += __shfl_xor_sync(0xffffffffu, aca.z, o);
        aca.w += __shfl_xor_sync(0xffffffffu, aca.w, o);
        acb.x += __shfl_xor_sync(0xffffffffu, acb.x, o);
        acb.y += __shfl_xor_sync(0xffffffffu, acb.y, o);
        acb.z += __shfl_xor_sync(0xffffffffu, acb.z, o);
        acb.w += __shfl_xor_sync(0xffffffffu, acb.w, o);
    }
    if (g == 0) {
        float4* op = (float4*)(out + (size_t)qrow * D_ + h * DH_);
        op[s * 2]     = make_float4(tf32r(aca.x), tf32r(aca.y), tf32r(aca.z), tf32r(aca.w));
        op[s * 2 + 1] = make_float4(tf32r(acb.x), tf32r(acb.y), tf32r(acb.z), tf32r(acb.w));
    }
}

// -------------------- host orchestration --------------------
extern "C" void kernel_launch(void* const* d_in, const int* in_sizes, int n_in,
                              void* d_out, int out_size)
{
    const float* tok   = (const float*)d_in[0];
    const float* W_in  = (const float*)d_in[1];
    const float* b_in  = (const float*)d_in[2];
    const float* Wq    = (const float*)d_in[3];
    const float* bq    = (const float*)d_in[4];
    const float* Wk    = (const float*)d_in[5];
    const float* bk    = (const float*)d_in[6];
    const float* Wv    = (const float*)d_in[7];
    const float* bv    = (const float*)d_in[8];
    const float* Wo    = (const float*)d_in[9];
    const float* bo    = (const float*)d_in[10];
    const float* ln1g  = (const float*)d_in[11];
    const float* ln1b  = (const float*)d_in[12];
    const float* ln2g  = (const float*)d_in[13];
    const float* ln2b  = (const float*)d_in[14];
    const float* W1    = (const float*)d_in[15];
    const float* b1    = (const float*)d_in[16];
    const float* W2    = (const float*)d_in[17];
    const float* b2    = (const float*)d_in[18];
    const float* W_out = (const float*)d_in[19];
    const float* b_out = (const float*)d_in[20];
    float* out = (float*)d_out;

    float *x, *h, *q, *k, *v, *ao, *ff;
    float *wq, *wk, *wv, *wo, *w1, *w2, *wout;
    cudaGetSymbolAddress((void**)&x,  g_x);
    cudaGetSymbolAddress((void**)&h,  g_h);
    cudaGetSymbolAddress((void**)&q,  g_q);
    cudaGetSymbolAddress((void**)&k,  g_k);
    cudaGetSymbolAddress((void**)&v,  g_v);
    cudaGetSymbolAddress((void**)&ao, g_ao);
    cudaGetSymbolAddress((void**)&ff, g_ff);
    cudaGetSymbolAddress((void**)&wq, g_wq);
    cudaGetSymbolAddress((void**)&wk, g_wk);
    cudaGetSymbolAddress((void**)&wv, g_wv);
    cudaGetSymbolAddress((void**)&wo, g_wo);
    cudaGetSymbolAddress((void**)&w1, g_w1);
    cudaGetSymbolAddress((void**)&w2, g_w2);
    cudaGetSymbolAddress((void**)&wout, g_wout);

    constexpr int SM_SMALL = 2 * 64 * 36 * 4 + 2 * 32 * 72 * 4;     // 36864
    constexpr int SM_BIG   = 2 * 128 * 36 * 4 + 2 * 32 * 136 * 4;   // 71680

    //            BM  BN  WM WN  RELU  RES   QKV3  QOUT  BIASF KSPLIT2 ROPEQK
    auto* kQKV = tgemm_kernel<64, 64, 2, 2, false, false, true,  false, true,  false, true >;
    auto* kRES = tgemm_kernel<64, 64, 2, 2, false, true,  false, false, true,  false, false>;
    auto* kFF1 = tgemm_kernel<128,128, 2, 2, true,  false, false, true,  true,  false, false>;
    auto* kFF2 = tgemm_kernel<64, 64, 2, 2, false, false, false, false, false, true,  false>;
    auto* kOUT = tgemm_kernel<128,128, 2, 2, false, false, false, false, true,  false, false>;
    cudaFuncSetAttribute(kQKV, cudaFuncAttributeMaxDynamicSharedMemorySize, SM_SMALL);
    cudaFuncSetAttribute(kRES, cudaFuncAttributeMaxDynamicSharedMemorySize, SM_SMALL);
    cudaFuncSetAttribute(kFF1, cudaFuncAttributeMaxDynamicSharedMemorySize, SM_BIG);
    cudaFuncSetAttribute(kFF2, cudaFuncAttributeMaxDynamicSharedMemorySize, SM_SMALL);
    cudaFuncSetAttribute(kOUT, cudaFuncAttributeMaxDynamicSharedMemorySize, SM_BIG);

    const dim3 gQKV(D_ / 64, M_ / 64, 3);     // (4, 64, 3)
    const dim3 gRES(D_ / 64, M_ / 64);        // (4, 64)
    const dim3 gFF1(FF_ / 128, M_ / 128);     // (16, 32)
    const dim3 gFF2(D_ / 64, M_ / 64, 2);     // (4, 64, 2) split-K
    const dim3 gO  (NOUT_ / 128, M_ / 128);   // (128, 32)

    // x = tok @ W_in + b_in
    embed_kernel<<<dim3(D_ / 128, M_ / 128), 256>>>(tok, W_in, b_in, x, M_, D_, 8);    // 0
    ln_kernel<<<M_ / 8, 256>>>(x, ln1g, ln1b, h);                                      // 1
    prequant_kernel<<<(PQ_ALL + 255) / 256, 256>>>(Wq, Wk, Wv, Wo, W1, W2, W_out);     // 2

    for (int l = 0; l < L_; l++) {
        kQKV<<<gQKV, 128, SM_SMALL>>>(h,                                               // 3 (l=0)
            wq + (size_t)l * D_ * D_, bq + l * D_, q, nullptr, D_, D_, D_,
            wk + (size_t)l * D_ * D_, bk + l * D_, k,
            wv + (size_t)l * D_ * D_, bv + l * D_, v);

        attn_kernel<<<(B_ * H_ * C_ * 32) / 128, 128>>>(q, k, v, ao);

        kRES<<<gRES, 128, SM_SMALL>>>(ao,
            wo + (size_t)l * D_ * D_, bo + l * D_, x, x, D_, D_, D_,
            nullptr, nullptr, nullptr, nullptr, nullptr, nullptr);

        ln_kernel<<<M_ / 8, 256>>>(x, ln2g + l * D_, ln2b + l * D_, h);

        kFF1<<<gFF1, 128, SM_BIG>>>(h,
            w1 + (size_t)l * D_ * FF_, b1 + l * FF_, ff, nullptr, FF_, D_, D_,
            nullptr, nullptr, nullptr, nullptr, nullptr, nullptr);

        kFF2<<<gFF2, 128, SM_SMALL>>>(ff,
            w2 + (size_t)l * FF_ * D_, nullptr, q, nullptr, D_, FF_ / 2, FF_,
            w2 + (size_t)l * FF_ * D_ + (size_t)(FF_ / 2) * D_, nullptr, k,
            nullptr, nullptr, nullptr);

        if (l + 1 < L_) {
            redln_kernel<<<M_ / 8, 256>>>(q, k, b2 + l * D_, x,
                                          ln1g + (l + 1) * D_, ln1b + (l + 1) * D_, h);
        } else {
            redq_kernel<<<(M_ * D_ / 4) / 256, 256>>>(q, k, b2 + l * D_, x, v);
        }
    }

    // out = xq @ W_out + b_out
    kOUT<<<gO, 128, SM_BIG>>>(v,
        wout, b_out, out, nullptr, NOUT_, D_, D_,
        nullptr, nullptr, nullptr, nullptr, nullptr, nullptr);
}

// round 15
// speedup vs baseline: 1.0368x; 1.0368x over previous
#include <cuda_runtime.h>
#include <math.h>
#include <stdint.h>

// Problem constants (fixed by setup_inputs)
#define B_      2
#define C_      2048
#define D_      256
#define H_      8
#define L_      4
#define FF_     2048
#define DH_     32
#define NOUT_   16384
#define M_      (B_ * C_)      // 4096
#define KTOK_   60

// -------------------- scratch --------------------
__device__ float g_x [M_ * D_];
__device__ float g_h [M_ * D_];
__device__ float g_q [M_ * D_];
__device__ float g_k [M_ * D_];
__device__ float g_v [M_ * D_];
__device__ float g_ao[M_ * D_];
__device__ float g_ff[M_ * FF_];
__device__ float g_cos[C_ * 16];
__device__ float g_sin[C_ * 16];
// pre-quantized (tf32) weights
__device__ float g_wq[L_ * D_ * D_];
__device__ float g_wk[L_ * D_ * D_];
__device__ float g_wv[L_ * D_ * D_];
__device__ float g_wo[L_ * D_ * D_];
__device__ float g_w1[L_ * D_ * FF_];
__device__ float g_w2[L_ * FF_ * D_];
__device__ float g_wout[D_ * NOUT_];

// TF32 input quantization (round-to-nearest-away), matching cuBLAS/XLA TF32 matmuls.
__device__ __forceinline__ float tf32r(float x) {
    float r;
    asm("cvt.rna.tf32.f32 %0, %1;" : "=f"(r) : "f"(x));
    return r;
}

__device__ __forceinline__ void cp16(uint32_t saddr, const float* gptr) {
    asm volatile("cp.async.cg.shared.global [%0], [%1], 16;" :: "r"(saddr), "l"(gptr));
}
__device__ __forceinline__ void cp_commit() {
    asm volatile("cp.async.commit_group;" ::: "memory");
}
template<int N>
__device__ __forceinline__ void cp_wait() {
    asm volatile("cp.async.wait_group %0;" :: "n"(N) : "memory");
}

// -------------------- fused weight-prequant + RoPE-tables kernel -----------------------
#define SEG_A  (L_ * D_ * D_ / 4)        // 65536 per qkv/o weight
#define SEG_W  (L_ * D_ * FF_ / 4)       // 524288 per w1/w2
#define SEG_O  (D_ * NOUT_ / 4)          // 1048576
#define PQ_TOTAL (4 * SEG_A + 2 * SEG_W + SEG_O)
#define PQ_ALL   (PQ_TOTAL + C_ * 16)

__global__ void prequant_kernel(
    const float* __restrict__ Wq, const float* __restrict__ Wk,
    const float* __restrict__ Wv, const float* __restrict__ Wo,
    const float* __restrict__ W1, const float* __restrict__ W2,
    const float* __restrict__ Wout)
{
    int i = blockIdx.x * blockDim.x + threadIdx.x;
    if (i >= PQ_ALL) return;
    if (i >= PQ_TOTAL) {
        const int t = i - PQ_TOTAL;
        const int fi = t & 15;
        const int c  = t >> 4;
        const float invf = (float)(1.0 / pow(10000.0, (double)fi / 16.0));
        const float angf = (float)c * invf;
        g_cos[t] = (float)cos((double)angf);
        g_sin[t] = (float)sin((double)angf);
        return;
    }
    const float* src; float* dst;
    if      (i < 1 * SEG_A)             { src = Wq;  dst = g_wq;   i -= 0 * SEG_A; }
    else if (i < 2 * SEG_A)             { src = Wk;  dst = g_wk;   i -= 1 * SEG_A; }
    else if (i < 3 * SEG_A)             { src = Wv;  dst = g_wv;   i -= 2 * SEG_A; }
    else if (i < 4 * SEG_A)             { src = Wo;  dst = g_wo;   i -= 3 * SEG_A; }
    else if (i < 4 * SEG_A + SEG_W)     { src = W1;  dst = g_w1;   i -= 4 * SEG_A; }
    else if (i < 4 * SEG_A + 2 * SEG_W) { src = W2;  dst = g_w2;   i -= 4 * SEG_A + SEG_W; }
    else                                { src = Wout;dst = g_wout; i -= 4 * SEG_A + 2 * SEG_W; }
    float4 a = ((const float4*)src)[i];
    a.x = tf32r(a.x); a.y = tf32r(a.y); a.z = tf32r(a.z); a.w = tf32r(a.w);
    ((float4*)dst)[i] = a;
}

// ==================== TF32 HMMA GEMM, 2-stage cp.async (proven R10 config) ==============
// All inputs PRE-QUANTIZED tf32 values. C = A@B [+bias] [+res] [relu] [tf32-out].
// KSPLIT2: blockIdx.z selects K-half. ROPEQK: fuse RoPE+quantize into epilogue for z<2.
template<int BM, int BN, int WM_, int WN_, bool RELU, bool RES, bool QKV3, bool QOUT,
         bool BIASF, bool KSPLIT2, bool ROPEQK>
__global__ void tgemm_kernel(
    const float* __restrict__ A,
    const float* __restrict__ B0, const float* __restrict__ bias0, float* __restrict__ C0,
    const float* __restrict__ res,
    int N, int K, int lda,
    const float* B1, const float* bias1, float* C1,
    const float* B2, const float* bias2, float* C2)
{
    constexpr int THREADS = WM_ * WN_ * 32;
    constexpr int AST = 36;
    constexpr int BST = BN + 8;
    constexpr int FM  = (BM / WM_) / 16;
    constexpr int FN  = (BN / WN_) / 8;

    extern __shared__ float smem[];
    float* As = smem;                     // [2][BM][AST]
    float* Bs = smem + 2 * BM * AST;      // [2][32][BST]

    const float* Ap = A;
    const float* Bm = B0;  const float* bias = bias0;  float* Cm = C0;
    if (QKV3) {
        if (blockIdx.z == 1)      { Bm = B1; bias = bias1; Cm = C1; }
        else if (blockIdx.z == 2) { Bm = B2; bias = bias2; Cm = C2; }
    }
    if (KSPLIT2) {
        if (blockIdx.z == 1) { Ap = A + K; Bm = B1; Cm = C1; }
    }

    const int tid  = threadIdx.x;
    const int warp = tid >> 5;
    const int lane = tid & 31;
    const int wm   = warp / WN_;
    const int wn   = warp % WN_;
    const int gid  = lane >> 2;
    const int tid4 = lane & 3;

    const int row0 = blockIdx.y * BM;
    const int col0 = blockIdx.x * BN;

    float acc[FM][FN][4];
#pragma unroll
    for (int i = 0; i < FM; i++)
#pragma unroll
        for (int j = 0; j < FN; j++)
#pragma unroll
            for (int t = 0; t < 4; t++) acc[i][j][t] = 0.f;

    const int nk = K >> 5;

    auto issue = [&](int t, int buf) {
        const int k0 = t << 5;
        float* Ad = As + buf * BM * AST;
        float* Bd = Bs + buf * 32 * BST;
#pragma unroll
        for (int i = 0; i < (BM * 8) / THREADS; i++) {
            const int idx = tid + i * THREADS;
            const int r   = idx >> 3;
            const int k4  = (idx & 7) * 4;
            cp16((uint32_t)__cvta_generic_to_shared(Ad + r * AST + k4),
                 Ap + (size_t)(row0 + r) * lda + k0 + k4);
        }
#pragma unroll
        for (int i = 0; i < (BN * 8) / THREADS; i++) {
            const int idx = tid + i * THREADS;
            const int kr  = idx / (BN / 4);
            const int c4  = (idx % (BN / 4)) * 4;
            cp16((uint32_t)__cvta_generic_to_shared(Bd + kr * BST + c4),
                 Bm + (size_t)(k0 + kr) * N + col0 + c4);
        }
        cp_commit();
    };

    issue(0, 0);
    for (int t = 0; t < nk; t++) {
        if (t + 1 < nk) { issue(t + 1, (t + 1) & 1); cp_wait<1>(); }
        else            { cp_wait<0>(); }
        __syncthreads();

        const float* Ab = As + (t & 1) * BM * AST;
        const float* Bb = Bs + (t & 1) * 32 * BST;
#pragma unroll
        for (int kk = 0; kk < 32; kk += 8) {
            uint32_t af[FM][4];
#pragma unroll
            for (int mf = 0; mf < FM; mf++) {
                const int ar = wm * (BM / WM_) + mf * 16 + gid;
                af[mf][0] = __float_as_uint(Ab[(ar    ) * AST + kk + tid4    ]);
                af[mf][1] = __float_as_uint(Ab[(ar + 8) * AST + kk + tid4    ]);
                af[mf][2] = __float_as_uint(Ab[(ar    ) * AST + kk + tid4 + 4]);
                af[mf][3] = __float_as_uint(Ab[(ar + 8) * AST + kk + tid4 + 4]);
            }
            uint32_t bf[FN][2];
#pragma unroll
            for (int nf = 0; nf < FN; nf++) {
                const int bc = wn * (BN / WN_) + nf * 8 + gid;
                bf[nf][0] = __float_as_uint(Bb[(kk + tid4    ) * BST + bc]);
                bf[nf][1] = __float_as_uint(Bb[(kk + tid4 + 4) * BST + bc]);
            }
#pragma unroll
            for (int mf = 0; mf < FM; mf++)
#pragma unroll
                for (int nf = 0; nf < FN; nf++) {
                    asm volatile(
                        "mma.sync.aligned.m16n8k8.row.col.f32.tf32.tf32.f32 "
                        "{%0,%1,%2,%3}, {%4,%5,%6,%7}, {%8,%9}, {%0,%1,%2,%3};"
                        : "+f"(acc[mf][nf][0]), "+f"(acc[mf][nf][1]),
                          "+f"(acc[mf][nf][2]), "+f"(acc[mf][nf][3])
                        : "r"(af[mf][0]), "r"(af[mf][1]), "r"(af[mf][2]), "r"(af[mf][3]),
                          "r"(bf[nf][0]), "r"(bf[nf][1]));
                }
        }
        __syncthreads();
    }

    // ---------------- Epilogue ----------------
    if (ROPEQK) {
        const bool doRope = (blockIdx.z < 2);
#pragma unroll
        for (int mf = 0; mf < FM; mf++) {
            const int r = row0 + wm * (BM / WM_) + mf * 16 + gid;
            float val[FN][4];
#pragma unroll
            for (int nf = 0; nf < FN; nf++) {
                const int c = col0 + wn * (BN / WN_) + nf * 8 + tid4 * 2;
                val[nf][0] = acc[mf][nf][0] + bias[c];
                val[nf][1] = acc[mf][nf][1] + bias[c + 1];
                val[nf][2] = acc[mf][nf][2] + bias[c];
                val[nf][3] = acc[mf][nf][3] + bias[c + 1];
            }
            if (doRope) {
                const int tok1 = r & (C_ - 1);
                const int tok2 = (r + 8) & (C_ - 1);
#pragma unroll
                for (int nf = 0; nf < 2; nf++) {
                    const int i0 = nf * 8 + tid4 * 2;
                    float cs, sn, t1, t2;
                    cs = g_cos[tok1 * 16 + i0];     sn = g_sin[tok1 * 16 + i0];
                    t1 = val[nf][0]; t2 = val[nf + 2][0];
                    val[nf][0]     = t1 * cs - t2 * sn;
                    val[nf + 2][0] = t1 * sn + t2 * cs;
                    cs = g_cos[tok1 * 16 + i0 + 1]; sn = g_sin[tok1 * 16 + i0 + 1];
                    t1 = val[nf][1]; t2 = val[nf + 2][1];
                    val[nf][1]     = t1 * cs - t2 * sn;
                    val[nf + 2][1] = t1 * sn + t2 * cs;
                    cs = g_cos[tok2 * 16 + i0];     sn = g_sin[tok2 * 16 + i0];
                    t1 = val[nf][2]; t2 = val[nf + 2][2];
                    val[nf][2]     = t1 * cs - t2 * sn;
                    val[nf + 2][2] = t1 * sn + t2 * cs;
                    cs = g_cos[tok2 * 16 + i0 + 1]; sn = g_sin[tok2 * 16 + i0 + 1];
                    t1 = val[nf][3]; t2 = val[nf + 2][3];
                    val[nf][3]     = t1 * cs - t2 * sn;
                    val[nf + 2][3] = t1 * sn + t2 * cs;
                }
#pragma unroll
                for (int nf = 0; nf < FN; nf++)
#pragma unroll
                    for (int t = 0; t < 4; t++) val[nf][t] = tf32r(val[nf][t]);
            }
#pragma unroll
            for (int nf = 0; nf < FN; nf++) {
                const int c = col0 + wn * (BN / WN_) + nf * 8 + tid4 * 2;
                *(float2*)(Cm + (size_t)r * N + c)       = make_float2(val[nf][0], val[nf][1]);
                *(float2*)(Cm + (size_t)(r + 8) * N + c) = make_float2(val[nf][2], val[nf][3]);
            }
        }
    } else {
#pragma unroll
        for (int mf = 0; mf < FM; mf++) {
            const int r = row0 + wm * (BM / WM_) + mf * 16 + gid;
#pragma unroll
            for (int nf = 0; nf < FN; nf++) {
                const int c = col0 + wn * (BN / WN_) + nf * 8 + tid4 * 2;
                float v0 = acc[mf][nf][0];
                float v1 = acc[mf][nf][1];
                float v2 = acc[mf][nf][2];
                float v3 = acc[mf][nf][3];
                if (BIASF) {
                    v0 += bias[c]; v1 += bias[c + 1]; v2 += bias[c]; v3 += bias[c + 1];
                }
                if (RES) {
                    const float2 r0 = *(const float2*)(res + (size_t)r * N + c);
                    const float2 r1 = *(const float2*)(res + (size_t)(r + 8) * N + c);
                    v0 += r0.x; v1 += r0.y; v2 += r1.x; v3 += r1.y;
                }
                if (RELU) {
                    v0 = fmaxf(v0, 0.f); v1 = fmaxf(v1, 0.f);
                    v2 = fmaxf(v2, 0.f); v3 = fmaxf(v3, 0.f);
                }
                if (QOUT) {
                    v0 = tf32r(v0); v1 = tf32r(v1); v2 = tf32r(v2); v3 = tf32r(v3);
                }
                *(float2*)(Cm + (size_t)r * N + c)       = make_float2(v0, v1);
                *(float2*)(Cm + (size_t)(r + 8) * N + c) = make_float2(v2, v3);
            }
        }
    }
}

// -------------------- fused FF2-reduce + layernorm (warp/row) --------------------------
__global__ __launch_bounds__(256) void redln_kernel(
    const float* __restrict__ p0, const float* __restrict__ p1,
    const float* __restrict__ b2, float* __restrict__ x,
    const float* __restrict__ g, const float* __restrict__ b, float* __restrict__ out)
{
    const int row  = blockIdx.x * 8 + (threadIdx.x >> 5);
    const int lane = threadIdx.x & 31;
    const size_t base = (size_t)row * D_;

    float4 a0, a1;
    {
        const float4 xa = ((const float4*)(x + base))[lane];
        const float4 xb = ((const float4*)(x + base))[lane + 32];
        const float4 pa = ((const float4*)(p0 + base))[lane];
        const float4 pb = ((const float4*)(p0 + base))[lane + 32];
        const float4 qa = ((const float4*)(p1 + base))[lane];
        const float4 qb = ((const float4*)(p1 + base))[lane + 32];
        const float4 ba = ((const float4*)b2)[lane];
        const float4 bb = ((const float4*)b2)[lane + 32];
        a0.x = xa.x + (pa.x + qa.x + ba.x);
        a0.y = xa.y + (pa.y + qa.y + ba.y);
        a0.z = xa.z + (pa.z + qa.z + ba.z);
        a0.w = xa.w + (pa.w + qa.w + ba.w);
        a1.x = xb.x + (pb.x + qb.x + bb.x);
        a1.y = xb.y + (pb.y + qb.y + bb.y);
        a1.z = xb.z + (pb.z + qb.z + bb.z);
        a1.w = xb.w + (pb.w + qb.w + bb.w);
        ((float4*)(x + base))[lane]      = a0;
        ((float4*)(x + base))[lane + 32] = a1;
    }

    float s  = a0.x + a0.y + a0.z + a0.w + a1.x + a1.y + a1.z + a1.w;
    float s2 = a0.x*a0.x + a0.y*a0.y + a0.z*a0.z + a0.w*a0.w
             + a1.x*a1.x + a1.y*a1.y + a1.z*a1.z + a1.w*a1.w;
#pragma unroll
    for (int o = 16; o > 0; o >>= 1) {
        s  += __shfl_xor_sync(0xffffffffu, s,  o);
        s2 += __shfl_xor_sync(0xffffffffu, s2, o);
    }
    const float mean = s  * (1.f / 256.f);
    const float var  = s2 * (1.f / 256.f) - mean * mean;
    const float rs   = rsqrtf(var + 1e-5f);

    const float4 g0 = ((const float4*)g)[lane];
    const float4 g1 = ((const float4*)g)[lane + 32];
    const float4 b0 = ((const float4*)b)[lane];
    const float4 b1 = ((const float4*)b)[lane + 32];
    float4* op = (float4*)(out + base);
    op[lane]      = make_float4(tf32r((a0.x-mean)*rs*g0.x + b0.x), tf32r((a0.y-mean)*rs*g0.y + b0.y),
                                tf32r((a0.z-mean)*rs*g0.z + b0.z), tf32r((a0.w-mean)*rs*g0.w + b0.w));
    op[lane + 32] = make_float4(tf32r((a1.x-mean)*rs*g1.x + b1.x), tf32r((a1.y-mean)*rs*g1.y + b1.y),
                                tf32r((a1.z-mean)*rs*g1.z + b1.z), tf32r((a1.w-mean)*rs*g1.w + b1.w));
}

// -------------------- fused final FF2-reduce + tf32 quantize ---------------------------
__global__ void redq_kernel(
    const float* __restrict__ p0, const float* __restrict__ p1,
    const float* __restrict__ b2, const float* __restrict__ x, float* __restrict__ xq)
{
    const int i = blockIdx.x * blockDim.x + threadIdx.x;
    const int c = i & (D_ / 4 - 1);
    const float4 a = ((const float4*)p0)[i];
    const float4 b = ((const float4*)p1)[i];
    const float4 bb = ((const float4*)b2)[c];
    const float4 xx = ((const float4*)x)[i];
    float4 o;
    o.x = tf32r(xx.x + (a.x + b.x + bb.x));
    o.y = tf32r(xx.y + (a.y + b.y + bb.y));
    o.z = tf32r(xx.z + (a.z + b.z + bb.z));
    o.w = tf32r(xx.w + (a.w + b.w + bb.w));
    ((float4*)xq)[i] = o;
}

// -------------------- FFMA GEMM for the K=8 embed only --------------------
__global__ __launch_bounds__(256) void embed_kernel(
    const float* __restrict__ A, const float* __restrict__ Bm,
    const float* __restrict__ bias, float* __restrict__ Cm, int M, int N, int K)
{
    __shared__ float As[8][128];
    __shared__ float Bs[8][128];
    const int tid  = threadIdx.x;
    const int tx   = tid & 15;
    const int ty   = tid >> 4;
    const int row0 = blockIdx.y * 128;
    const int col0 = blockIdx.x * 128;
    const int aRow = tid >> 1;
    const int aCol = (tid & 1) * 4;
    const int bRow = tid >> 5;
    const int bCol = (tid & 31) * 4;

    float acc[8][8];
#pragma unroll
    for (int i = 0; i < 8; i++)
#pragma unroll
        for (int j = 0; j < 8; j++) acc[i][j] = 0.f;

    for (int k0 = 0; k0 < K; k0 += 8) {
        float4 a4 = *(const float4*)(A + (size_t)(row0 + aRow) * K + k0 + aCol);
        As[aCol + 0][aRow] = tf32r(a4.x);
        As[aCol + 1][aRow] = tf32r(a4.y);
        As[aCol + 2][aRow] = tf32r(a4.z);
        As[aCol + 3][aRow] = tf32r(a4.w);
        float4 b4 = *(const float4*)(Bm + (size_t)(k0 + bRow) * N + col0 + bCol);
        Bs[bRow][bCol + 0] = tf32r(b4.x);
        Bs[bRow][bCol + 1] = tf32r(b4.y);
        Bs[bRow][bCol + 2] = tf32r(b4.z);
        Bs[bRow][bCol + 3] = tf32r(b4.w);
        __syncthreads();
#pragma unroll
        for (int kk = 0; kk < 8; kk++) {
            float ra[8], rb[8];
#pragma unroll
            for (int i = 0; i < 8; i++) ra[i] = As[kk][ty * 8 + i];
#pragma unroll
            for (int j = 0; j < 8; j++) rb[j] = Bs[kk][tx * 8 + j];
#pragma unroll
            for (int i = 0; i < 8; i++)
#pragma unroll
                for (int j = 0; j < 8; j++)
                    acc[i][j] += ra[i] * rb[j];
        }
        __syncthreads();
    }
#pragma unroll
    for (int i = 0; i < 8; i++) {
        int r = row0 + ty * 8 + i;
#pragma unroll
        for (int j = 0; j < 8; j++) {
            int c = col0 + tx * 8 + j;
            Cm[(size_t)r * N + c] = acc[i][j] + bias[c];
        }
    }
}

// -------------------- layernorm (warp/row, float4); OUTPUT IS TF32-QUANTIZED -----------
__global__ __launch_bounds__(256) void ln_kernel(
    const float* __restrict__ x, const float* __restrict__ g,
    const float* __restrict__ b, float* __restrict__ out)
{
    const int row  = blockIdx.x * 8 + (threadIdx.x >> 5);
    const int lane = threadIdx.x & 31;
    const float4* xp = (const float4*)(x + (size_t)row * D_);
    const float4 a0 = xp[lane];
    const float4 a1 = xp[lane + 32];

    float s  = a0.x + a0.y + a0.z + a0.w + a1.x + a1.y + a1.z + a1.w;
    float s2 = a0.x*a0.x + a0.y*a0.y + a0.z*a0.z + a0.w*a0.w
             + a1.x*a1.x + a1.y*a1.y + a1.z*a1.z + a1.w*a1.w;
#pragma unroll
    for (int o = 16; o > 0; o >>= 1) {
        s  += __shfl_xor_sync(0xffffffffu, s,  o);
        s2 += __shfl_xor_sync(0xffffffffu, s2, o);
    }
    const float mean = s  * (1.f / 256.f);
    const float var  = s2 * (1.f / 256.f) - mean * mean;
    const float rs   = rsqrtf(var + 1e-5f);

    const float4 g0 = ((const float4*)g)[lane];
    const float4 g1 = ((const float4*)g)[lane + 32];
    const float4 b0 = ((const float4*)b)[lane];
    const float4 b1 = ((const float4*)b)[lane + 32];
    float4* op = (float4*)(out + (size_t)row * D_);
    op[lane]      = make_float4(tf32r((a0.x-mean)*rs*g0.x + b0.x), tf32r((a0.y-mean)*rs*g0.y + b0.y),
                                tf32r((a0.z-mean)*rs*g0.z + b0.z), tf32r((a0.w-mean)*rs*g0.w + b0.w));
    op[lane + 32] = make_float4(tf32r((a1.x-mean)*rs*g1.x + b1.x), tf32r((a1.y-mean)*rs*g1.y + b1.y),
                                tf32r((a1.z-mean)*rs*g1.z + b1.z), tf32r((a1.w-mean)*rs*g1.w + b1.w));
}

// -------------------- windowed circular attention (R10 proven version) -----------------
// One warp per (b,h,q). lane = g*8+s: group g handles key j0+g, lane-quad s handles
// dims 4s..4s+3 via float4. 4 keys/iter, 3-shfl group reduction.
__global__ __launch_bounds__(128) void attn_kernel(
    const float* __restrict__ q, const float* __restrict__ k,
    const float* __restrict__ v, float* __restrict__ out)
{
    __shared__ float wbuf[4][64];
    const int warp = (blockIdx.x * blockDim.x + threadIdx.x) >> 5;  // (b,h,c)
    const int wib  = (threadIdx.x >> 5);
    const int lane = threadIdx.x & 31;
    const int g    = lane >> 3;
    const int s    = lane & 7;
    const int c = warp & (C_ - 1);
    const int h = (warp >> 11) & (H_ - 1);
    const int b = warp >> 14;
    const int qrow = b * C_ + c;
    const float scale = 0.17677669529663687f;                       // 1/sqrt(32)

    const float4 q4 = ((const float4*)(q + (size_t)qrow * D_ + h * DH_))[s];

    // Phase 1: scores for 4 keys per iteration
#pragma unroll 3
    for (int j0 = 0; j0 < KTOK_; j0 += 4) {
        const int j = j0 + g;
        int kc = c - j; if (kc < 0) kc += C_;
        const float4 k4 = ((const float4*)(k + (size_t)(b * C_ + kc) * D_ + h * DH_))[s];
        float p = q4.x * k4.x + q4.y * k4.y + q4.z * k4.z + q4.w * k4.w;
        p += __shfl_xor_sync(0xffffffffu, p, 1);
        p += __shfl_xor_sync(0xffffffffu, p, 2);
        p += __shfl_xor_sync(0xffffffffu, p, 4);
        if (s == 0) wbuf[wib][j] = p * scale;
    }
    __syncwarp();

    // Phase 2: max + denom (parallel over lanes)
    const float v1 = wbuf[wib][lane];
    const float v2 = (lane < KTOK_ - 32) ? wbuf[wib][lane + 32] : -INFINITY;
    float m = fmaxf(v1, v2);
#pragma unroll
    for (int o = 16; o > 0; o >>= 1) m = fmaxf(m, __shfl_xor_sync(0xffffffffu, m, o));
    const float p1 = __expf(v1 - m);
    const float p2 = (lane < KTOK_ - 32) ? __expf(v2 - m) : 0.f;
    wbuf[wib][lane] = p1;
    if (lane < KTOK_ - 32) wbuf[wib][lane + 32] = p2;
    float d = p1 + p2;
#pragma unroll
    for (int o = 16; o > 0; o >>= 1) d += __shfl_xor_sync(0xffffffffu, d, o);
    const float invd = 1.f / d;
    __syncwarp();

    // Phase 3: output accumulation, 4 keys per iteration
    float4 acc = make_float4(0.f, 0.f, 0.f, 0.f);
#pragma unroll 3
    for (int j0 = 0; j0 < KTOK_; j0 += 4) {
        const int j = j0 + g;
        int kc = c - j; if (kc < 0) kc += C_;
        const float4 v4 = ((const float4*)(v + (size_t)(b * C_ + kc) * D_ + h * DH_))[s];
        const float w = tf32r(wbuf[wib][j] * invd);
        acc.x += w * tf32r(v4.x);
        acc.y += w * tf32r(v4.y);
        acc.z += w * tf32r(v4.z);
        acc.w += w * tf32r(v4.w);
    }
#pragma unroll
    for (int o = 8; o <= 16; o <<= 1) {
        acc.x += __shfl_xor_sync(0xffffffffu, acc.x, o);
        acc.y += __shfl_xor_sync(0xffffffffu, acc.y, o);
        acc.z += __shfl_xor_sync(0xffffffffu, acc.z, o);
        acc.w += __shfl_xor_sync(0xffffffffu, acc.w, o);
    }
    if (g == 0)
        ((float4*)(out + (size_t)qrow * D_ + h * DH_))[s] =
            make_float4(tf32r(acc.x), tf32r(acc.y), tf32r(acc.z), tf32r(acc.w));
}

// -------------------- host orchestration --------------------
extern "C" void kernel_launch(void* const* d_in, const int* in_sizes, int n_in,
                              void* d_out, int out_size)
{
    const float* tok   = (const float*)d_in[0];
    const float* W_in  = (const float*)d_in[1];
    const float* b_in  = (const float*)d_in[2];
    const float* Wq    = (const float*)d_in[3];
    const float* bq    = (const float*)d_in[4];
    const float* Wk    = (const float*)d_in[5];
    const float* bk    = (const float*)d_in[6];
    const float* Wv    = (const float*)d_in[7];
    const float* bv    = (const float*)d_in[8];
    const float* Wo    = (const float*)d_in[9];
    const float* bo    = (const float*)d_in[10];
    const float* ln1g  = (const float*)d_in[11];
    const float* ln1b  = (const float*)d_in[12];
    const float* ln2g  = (const float*)d_in[13];
    const float* ln2b  = (const float*)d_in[14];
    const float* W1    = (const float*)d_in[15];
    const float* b1    = (const float*)d_in[16];
    const float* W2    = (const float*)d_in[17];
    const float* b2    = (const float*)d_in[18];
    const float* W_out = (const float*)d_in[19];
    const float* b_out = (const float*)d_in[20];
    float* out = (float*)d_out;

    float *x, *h, *q, *k, *v, *ao, *ff;
    float *wq, *wk, *wv, *wo, *w1, *w2, *wout;
    cudaGetSymbolAddress((void**)&x,  g_x);
    cudaGetSymbolAddress((void**)&h,  g_h);
    cudaGetSymbolAddress((void**)&q,  g_q);
    cudaGetSymbolAddress((void**)&k,  g_k);
    cudaGetSymbolAddress((void**)&v,  g_v);
    cudaGetSymbolAddress((void**)&ao, g_ao);
    cudaGetSymbolAddress((void**)&ff, g_ff);
    cudaGetSymbolAddress((void**)&wq, g_wq);
    cudaGetSymbolAddress((void**)&wk, g_wk);
    cudaGetSymbolAddress((void**)&wv, g_wv);
    cudaGetSymbolAddress((void**)&wo, g_wo);
    cudaGetSymbolAddress((void**)&w1, g_w1);
    cudaGetSymbolAddress((void**)&w2, g_w2);
    cudaGetSymbolAddress((void**)&wout, g_wout);

    constexpr int SM_SMALL = 2 * 64 * 36 * 4 + 2 * 32 * 72 * 4;     // 36864
    constexpr int SM_BIG   = 2 * 128 * 36 * 4 + 2 * 32 * 136 * 4;   // 71680

    //            BM  BN  WM WN  RELU  RES   QKV3  QOUT  BIASF KSPLIT2 ROPEQK
    auto* kQKV = tgemm_kernel<64, 64, 2, 2, false, false, true,  false, true,  false, true >;
    auto* kRES = tgemm_kernel<64, 64, 2, 2, false, true,  false, false, true,  false, false>;
    auto* kFF1 = tgemm_kernel<128,128, 2, 2, true,  false, false, true,  true,  false, false>;
    auto* kFF2 = tgemm_kernel<64, 64, 2, 2, false, false, false, false, false, true,  false>;
    auto* kOUT = tgemm_kernel<128,128, 2, 2, false, false, false, false, true,  false, false>;
    cudaFuncSetAttribute(kQKV, cudaFuncAttributeMaxDynamicSharedMemorySize, SM_SMALL);
    cudaFuncSetAttribute(kRES, cudaFuncAttributeMaxDynamicSharedMemorySize, SM_SMALL);
    cudaFuncSetAttribute(kFF1, cudaFuncAttributeMaxDynamicSharedMemorySize, SM_BIG);
    cudaFuncSetAttribute(kFF2, cudaFuncAttributeMaxDynamicSharedMemorySize, SM_SMALL);
    cudaFuncSetAttribute(kOUT, cudaFuncAttributeMaxDynamicSharedMemorySize, SM_BIG);

    const dim3 gQKV(D_ / 64, M_ / 64, 3);     // (4, 64, 3)
    const dim3 gRES(D_ / 64, M_ / 64);        // (4, 64)
    const dim3 gFF1(FF_ / 128, M_ / 128);     // (16, 32)
    const dim3 gFF2(D_ / 64, M_ / 64, 2);     // (4, 64, 2) split-K
    const dim3 gO  (NOUT_ / 128, M_ / 128);   // (128, 32)

    // x = tok @ W_in + b_in
    embed_kernel<<<dim3(D_ / 128, M_ / 128), 256>>>(tok, W_in, b_in, x, M_, D_, 8);    // 0
    ln_kernel<<<M_ / 8, 256>>>(x, ln1g, ln1b, h);                                      // 1
    prequant_kernel<<<(PQ_ALL + 255) / 256, 256>>>(Wq, Wk, Wv, Wo, W1, W2, W_out);     // 2

    for (int l = 0; l < L_; l++) {
        kQKV<<<gQKV, 128, SM_SMALL>>>(h,                                               // 3 (l=0)
            wq + (size_t)l * D_ * D_, bq + l * D_, q, nullptr, D_, D_, D_,
            wk + (size_t)l * D_ * D_, bk + l * D_, k,
            wv + (size_t)l * D_ * D_, bv + l * D_, v);

        attn_kernel<<<(B_ * H_ * C_ * 32) / 128, 128>>>(q, k, v, ao);

        kRES<<<gRES, 128, SM_SMALL>>>(ao,
            wo + (size_t)l * D_ * D_, bo + l * D_, x, x, D_, D_, D_,
            nullptr, nullptr, nullptr, nullptr, nullptr, nullptr);

        ln_kernel<<<M_ / 8, 256>>>(x, ln2g + l * D_, ln2b + l * D_, h);

        kFF1<<<gFF1, 128, SM_BIG>>>(h,
            w1 + (size_t)l * D_ * FF_, b1 + l * FF_, ff, nullptr, FF_, D_, D_,
            nullptr, nullptr, nullptr, nullptr, nullptr, nullptr);

        kFF2<<<gFF2, 128, SM_SMALL>>>(ff,
            w2 + (size_t)l * FF_ * D_, nullptr, q, nullptr, D_, FF_ / 2, FF_,
            w2 + (size_t)l * FF_ * D_ + (size_t)(FF_ / 2) * D_, nullptr, k,
            nullptr, nullptr, nullptr);

        if (l + 1 < L_) {
            redln_kernel<<<M_ / 8, 256>>>(q, k, b2 + l * D_, x,
                                          ln1g + (l + 1) * D_, ln1b + (l + 1) * D_, h);
        } else {
            redq_kernel<<<(M_ * D_ / 4) / 256, 256>>>(q, k, b2 + l * D_, x, v);
        }
    }

    // out = xq @ W_out + b_out
    kOUT<<<gO, 128, SM_BIG>>>(v,
        wout, b_out, out, nullptr, NOUT_, D_, D_,
        nullptr, nullptr, nullptr, nullptr, nullptr, nullptr);
}